// round 6
// baseline (speedup 1.0000x reference)
#include <cuda_runtime.h>

// ---------------------------------------------------------------------------
// RadianceTransformer2 fully-fused fp32 kernel (f32x2 packed FMA pipe).
// One CTA (256 threads) owns 8 rays = 64 tokens; all activations in smem.
// ---------------------------------------------------------------------------

#define B_RAYS   32768
#define RAYS_CTA 8
#define TOK      64            // tokens per CTA (8 rays * 8)
#define P        68            // smem row pitch in floats (bank-conflict pad, 16B aligned)

// d_out layout: color (B*3), sigma (B), out (B*512), attn (B*1024)
#define COLOR_OFF 0
#define SIG_OFF   ((size_t)B_RAYS * 3)
#define OUT_OFF   ((size_t)B_RAYS * 4)
#define ATTN_OFF  ((size_t)B_RAYS * 516)

// smem float offsets
#define XS_O   0
#define ACC_O  4352
#define QB_O   8704
#define KB_O   13056
#define VB_O   17408
#define WST_O  21760
#define PB_O   25856          // 64 x 9
#define QS_O   26432          // 8 x 68
#define SMEM_FLOATS 26976
#define SMEM_BYTES  (SMEM_FLOATS * 4)

typedef unsigned long long u64;

__device__ __forceinline__ u64 pk2(float x, float y) {
    u64 r; asm("mov.b64 %0, {%1,%2};" : "=l"(r) : "f"(x), "f"(y)); return r;
}
__device__ __forceinline__ void up2(u64 v, float& x, float& y) {
    asm("mov.b64 {%0,%1}, %2;" : "=f"(x), "=f"(y) : "l"(v));
}
__device__ __forceinline__ void fma2(u64& a, u64 b, u64 c) {
    asm("fma.rn.f32x2 %0, %1, %2, %0;" : "+l"(a) : "l"(b), "l"(c));
}

struct Params {
    const float *query, *latent, *W1, *b1;
    const float *Wq, *bq, *Wk, *bk, *Wv, *bv, *Wo, *bo;
    const float *fW1, *fb1, *fW2, *fb2;
    const float *g1, *be1, *g2, *be2;
    const float *cWq, *cbq, *cWk, *cbk, *cWv, *cbv, *cWo, *cbo;
    const float *Wc, *bc, *Wsig, *bs;
};

// Stage a 64x64 weight tile (row stride `stride` floats in gmem) into Wst[64][64]
__device__ __forceinline__ void stagew(float* Wst, const float* __restrict__ src, int stride) {
    int tx = threadIdx.x;
    #pragma unroll
    for (int rep = 0; rep < 4; ++rep) {
        int i = rep * 256 + tx;
        int d = i >> 4, cv = (i & 15) << 2;
        *(float4*)(Wst + d * 64 + cv) = __ldg((const float4*)(src + (size_t)d * stride + cv));
    }
}

// C[64x64(pitch P)] = (ACC ? C : bias) + A[64x64(pitch P)] @ Wst[64x64]
// per thread: 1 token x 16 cols; packed f32x2 accumulate
template <bool ACC, bool RELU>
__device__ __forceinline__ void gemm64(const float* __restrict__ A,
                                       const float* __restrict__ Wst,
                                       const float* __restrict__ biasg,
                                       float* __restrict__ C) {
    const int tx = threadIdx.x;
    const int t  = tx >> 2;
    const int j0 = (tx & 3) << 4;
    u64 acc[8];
    if (ACC) {
        const ulonglong2* c = (const ulonglong2*)(C + t * P + j0);
        #pragma unroll
        for (int q = 0; q < 4; ++q) { ulonglong2 v = c[q]; acc[2*q] = v.x; acc[2*q+1] = v.y; }
    } else {
        const float2* b2 = (const float2*)(biasg + j0);
        #pragma unroll
        for (int k = 0; k < 8; ++k) { float2 b = __ldg(b2 + k); acc[k] = pk2(b.x, b.y); }
    }
    const float* arow = A + t * P;
    #pragma unroll 8
    for (int d = 0; d < 64; ++d) {
        float a = arow[d];
        u64 ap = pk2(a, a);
        const ulonglong2* w = (const ulonglong2*)(Wst + d * 64 + j0);
        ulonglong2 w0 = w[0], w1 = w[1], w2 = w[2], w3 = w[3];
        fma2(acc[0], ap, w0.x); fma2(acc[1], ap, w0.y);
        fma2(acc[2], ap, w1.x); fma2(acc[3], ap, w1.y);
        fma2(acc[4], ap, w2.x); fma2(acc[5], ap, w2.y);
        fma2(acc[6], ap, w3.x); fma2(acc[7], ap, w3.y);
    }
    if (RELU) {
        #pragma unroll
        for (int k = 0; k < 8; ++k) {
            float x, y; up2(acc[k], x, y);
            acc[k] = pk2(fmaxf(x, 0.f), fmaxf(y, 0.f));
        }
    }
    ulonglong2* o = (ulonglong2*)(C + t * P + j0);
    o[0] = make_ulonglong2(acc[0], acc[1]);
    o[1] = make_ulonglong2(acc[2], acc[3]);
    o[2] = make_ulonglong2(acc[4], acc[5]);
    o[3] = make_ulonglong2(acc[6], acc[7]);
}

// Qb[64x64] = P[64x8] @ Vb (per-ray 8x8 attention applied to V)
__device__ __forceinline__ void pv64(const float* __restrict__ Pb,
                                     const float* __restrict__ Vb,
                                     float* __restrict__ Qb) {
    const int tx = threadIdx.x;
    const int t  = tx >> 2;
    const int j0 = (tx & 3) << 4;
    const int rbase = t & ~7;
    u64 acc[8];
    #pragma unroll
    for (int k = 0; k < 8; ++k) acc[k] = 0ull;
    #pragma unroll
    for (int j = 0; j < 8; ++j) {
        float pp = Pb[t * 9 + j];
        u64 pq = pk2(pp, pp);
        const ulonglong2* v = (const ulonglong2*)(Vb + (rbase + j) * P + j0);
        ulonglong2 v0 = v[0], v1 = v[1], v2 = v[2], v3 = v[3];
        fma2(acc[0], pq, v0.x); fma2(acc[1], pq, v0.y);
        fma2(acc[2], pq, v1.x); fma2(acc[3], pq, v1.y);
        fma2(acc[4], pq, v2.x); fma2(acc[5], pq, v2.y);
        fma2(acc[6], pq, v3.x); fma2(acc[7], pq, v3.y);
    }
    ulonglong2* o = (ulonglong2*)(Qb + t * P + j0);
    o[0] = make_ulonglong2(acc[0], acc[1]);
    o[1] = make_ulonglong2(acc[2], acc[3]);
    o[2] = make_ulonglong2(acc[4], acc[5]);
    o[3] = make_ulonglong2(acc[6], acc[7]);
}

// Xs = LayerNorm(Acc + Xs) * g + b  (per 64-wide token row; one thread per row)
__device__ __forceinline__ void ln_res(float* __restrict__ Xs, const float* __restrict__ Acc,
                                       const float* __restrict__ gg, const float* __restrict__ bb) {
    int tx = threadIdx.x;
    if (tx < 64) {
        const float4* x4 = (const float4*)(Xs + tx * P);
        const float4* a4 = (const float4*)(Acc + tx * P);
        float s = 0.f, s2 = 0.f;
        #pragma unroll
        for (int q = 0; q < 16; ++q) {
            float4 x = x4[q], a = a4[q];
            float v0 = x.x + a.x, v1 = x.y + a.y, v2 = x.z + a.z, v3 = x.w + a.w;
            s  += (v0 + v1) + (v2 + v3);
            s2 += v0 * v0 + v1 * v1 + v2 * v2 + v3 * v3;
        }
        float mean = s * 0.015625f;
        float var  = s2 * 0.015625f - mean * mean;
        float w = rsqrtf(var + 1e-5f);
        float4* xo = (float4*)(Xs + tx * P);
        const float4* g4 = (const float4*)gg;
        const float4* b4 = (const float4*)bb;
        #pragma unroll
        for (int q = 0; q < 16; ++q) {
            float4 x = x4[q], a = a4[q];
            float4 g = __ldg(g4 + q), b = __ldg(b4 + q);
            float4 o;
            o.x = (x.x + a.x - mean) * w * g.x + b.x;
            o.y = (x.y + a.y - mean) * w * g.y + b.y;
            o.z = (x.z + a.z - mean) * w * g.z + b.z;
            o.w = (x.w + a.w - mean) * w * g.w + b.w;
            xo[q] = o;
        }
    }
}

__global__ void __launch_bounds__(256, 2)
radiance_fused_kernel(Params p, float* __restrict__ out) {
    extern __shared__ float sm[];
    float* Xs  = sm + XS_O;
    float* Acc = sm + ACC_O;
    float* Qb  = sm + QB_O;
    float* Kb  = sm + KB_O;
    float* Vb  = sm + VB_O;
    float* Wst = sm + WST_O;
    float* Pb  = sm + PB_O;
    float* qs  = sm + QS_O;

    const int rb = blockIdx.x;          // ray-block: rays rb*8 .. rb*8+7
    const int tx = threadIdx.x;

    // ---------------- layer 0: Xs = relu(latent @ W1 + b1) ----------------
    for (int i = tx; i < 4096; i += 256) Acc[(i >> 6) * P + (i & 63)] = __ldg(p.b1 + (i & 63));
    for (int c = 0; c < 8; ++c) {
        __syncthreads();
        stagew(Wst, p.W1 + c * 64 * 64, 64);
        #pragma unroll
        for (int rep = 0; rep < 4; ++rep) {
            int i = rep * 256 + tx;
            int row = i >> 4, cv = (i & 15) << 2;
            *(float4*)(Xs + row * P + cv) =
                __ldg((const float4*)(p.latent + ((size_t)(rb * 64 + row)) * 512 + c * 64 + cv));
        }
        __syncthreads();
        gemm64<true, false>(Xs, Wst, nullptr, Acc);
    }
    __syncthreads();
    for (int i = tx; i < 4096; i += 256) {
        int t = i >> 6, j = i & 63;
        Xs[t * P + j] = fmaxf(Acc[t * P + j], 0.f);
    }
    __syncthreads();

    // ---------------- 4 transformer layers ----------------
    for (int l = 0; l < 4; ++l) {
        for (int i = tx; i < 4096; i += 256)
            Acc[(i >> 6) * P + (i & 63)] = __ldg(p.bo + l * 64 + (i & 63));
        __syncthreads();

        for (int h = 0; h < 4; ++h) {
            stagew(Wst, p.Wq + (size_t)l * 64 * 256 + h * 64, 256); __syncthreads();
            gemm64<false, false>(Xs, Wst, p.bq + l * 256 + h * 64, Qb); __syncthreads();
            stagew(Wst, p.Wk + (size_t)l * 64 * 256 + h * 64, 256); __syncthreads();
            gemm64<false, false>(Xs, Wst, p.bk + l * 256 + h * 64, Kb); __syncthreads();
            stagew(Wst, p.Wv + (size_t)l * 64 * 256 + h * 64, 256); __syncthreads();
            gemm64<false, false>(Xs, Wst, p.bv + l * 256 + h * 64, Vb); __syncthreads();

            // scores: 8 rays x 8 x 8
            for (int e = tx; e < 512; e += 256) {
                int r = e >> 6, qi = (e >> 3) & 7, kj = e & 7;
                const float4* q4 = (const float4*)(Qb + (r * 8 + qi) * P);
                const float4* k4 = (const float4*)(Kb + (r * 8 + kj) * P);
                float s = 0.f;
                #pragma unroll
                for (int d = 0; d < 16; ++d) {
                    float4 a = q4[d], b = k4[d];
                    s += a.x * b.x + a.y * b.y + a.z * b.z + a.w * b.w;
                }
                Pb[(r * 8 + qi) * 9 + kj] = s * 0.125f;
            }
            __syncthreads();

            // softmax + write attn probs
            if (tx < 64) {
                float* pr = Pb + tx * 9;
                float m = pr[0];
                #pragma unroll
                for (int j = 1; j < 8; ++j) m = fmaxf(m, pr[j]);
                float ex[8]; float ssum = 0.f;
                #pragma unroll
                for (int j = 0; j < 8; ++j) { float e = expf(pr[j] - m); ex[j] = e; ssum += e; }
                float inv = 1.f / ssum;
                int rayg = rb * 8 + (tx >> 3);
                int qi = tx & 7;
                size_t base = ATTN_OFF + (size_t)rayg * 1024 + (size_t)l * 256 + h * 64 + qi * 8;
                #pragma unroll
                for (int j = 0; j < 8; ++j) { float v = ex[j] * inv; pr[j] = v; out[base + j] = v; }
            }
            __syncthreads();

            pv64(Pb, Vb, Qb);                 // Qb := per-head attention output
            __syncthreads();
            stagew(Wst, p.Wo + (size_t)l * 256 * 64 + h * 64 * 64, 64); __syncthreads();
            gemm64<true, false>(Qb, Wst, nullptr, Acc);     // Acc += head @ Wo_h
            __syncthreads();
        }

        ln_res(Xs, Acc, p.g1 + l * 64, p.be1 + l * 64); __syncthreads();

        stagew(Wst, p.fW1 + (size_t)l * 64 * 64, 64); __syncthreads();
        gemm64<false, true>(Xs, Wst, p.fb1 + l * 64, Qb); __syncthreads();
        stagew(Wst, p.fW2 + (size_t)l * 64 * 64, 64); __syncthreads();
        gemm64<false, false>(Qb, Wst, p.fb2 + l * 64, Acc); __syncthreads();

        ln_res(Xs, Acc, p.g2 + l * 64, p.be2 + l * 64); __syncthreads();
    }

    // ---------------- out copy ----------------
    #pragma unroll
    for (int rep = 0; rep < 4; ++rep) {
        int i = rep * 256 + tx;
        int row = i >> 4, cv = (i & 15) << 2;
        *(float4*)(out + OUT_OFF + (size_t)(rb * 64 + row) * 64 + cv) =
            *(const float4*)(Xs + row * P + cv);
    }

    // ---------------- sigma = max_t(out) @ Wsig + bs ----------------
    if (tx < 64) {
        int r = tx >> 3, jg = tx & 7;
        float s = 0.f;
        #pragma unroll
        for (int jj = 0; jj < 8; ++jj) {
            int j = jg * 8 + jj;
            float m = Xs[(r * 8) * P + j];
            #pragma unroll
            for (int t = 1; t < 8; ++t) m = fmaxf(m, Xs[(r * 8 + t) * P + j]);
            s += m * __ldg(p.Wsig + j);
        }
        Pb[r * 9 + jg] = s;
    }
    __syncthreads();
    if (tx < 8) {
        float s = __ldg(p.bs);
        #pragma unroll
        for (int jg = 0; jg < 8; ++jg) s += Pb[tx * 9 + jg];
        out[SIG_OFF + (size_t)rb * 8 + tx] = s;
    }

    // ---------------- cross attention + color ----------------
    if (tx < 128) {
        int r = tx >> 4, cv = (tx & 15) << 2;
        *(float4*)(qs + r * P + cv) =
            __ldg((const float4*)(p.query + (size_t)(rb * 8 + r) * 64 + cv));
    }
    for (int e = tx; e < 512; e += 256)
        Acc[(e >> 6) * P + (e & 63)] = __ldg(p.cbo + (e & 63));   // cAcc rows 0..7
    __syncthreads();

    for (int h = 0; h < 4; ++h) {
        // Qc (rows 8..15 of Acc)
        stagew(Wst, p.cWq + h * 64, 256); __syncthreads();
        for (int e = tx; e < 512; e += 256) {
            int r = e >> 6, j = e & 63;
            float s = __ldg(p.cbq + h * 64 + j);
            #pragma unroll 8
            for (int d = 0; d < 64; ++d) s += qs[r * P + d] * Wst[d * 64 + j];
            Acc[(8 + r) * P + j] = s;
        }
        __syncthreads();
        stagew(Wst, p.cWk + h * 64, 256); __syncthreads();
        gemm64<false, false>(Xs, Wst, p.cbk + h * 64, Kb); __syncthreads();
        stagew(Wst, p.cWv + h * 64, 256); __syncthreads();
        gemm64<false, false>(Xs, Wst, p.cbv + h * 64, Vb); __syncthreads();

        if (tx < 64) {
            int r = tx >> 3, j = tx & 7;
            const float4* q4 = (const float4*)(Acc + (8 + r) * P);
            const float4* k4 = (const float4*)(Kb + (r * 8 + j) * P);
            float s = 0.f;
            #pragma unroll
            for (int d = 0; d < 16; ++d) {
                float4 a = q4[d], b = k4[d];
                s += a.x * b.x + a.y * b.y + a.z * b.z + a.w * b.w;
            }
            Pb[r * 9 + j] = s * 0.125f;
        }
        __syncthreads();
        if (tx < 8) {
            float* pr = Pb + tx * 9;
            float m = pr[0];
            #pragma unroll
            for (int j = 1; j < 8; ++j) m = fmaxf(m, pr[j]);
            float ssum = 0.f;
            #pragma unroll
            for (int j = 0; j < 8; ++j) { float e = expf(pr[j] - m); pr[j] = e; ssum += e; }
            float inv = 1.f / ssum;
            #pragma unroll
            for (int j = 0; j < 8; ++j) pr[j] *= inv;
        }
        __syncthreads();
        // outh (rows 16..23 of Acc)
        for (int e = tx; e < 512; e += 256) {
            int r = e >> 6, jc = e & 63;
            float s = 0.f;
            #pragma unroll
            for (int j = 0; j < 8; ++j) s += Pb[r * 9 + j] * Vb[(r * 8 + j) * P + jc];
            Acc[(16 + r) * P + jc] = s;
        }
        __syncthreads();
        stagew(Wst, p.cWo + h * 64 * 64, 64); __syncthreads();
        for (int e = tx; e < 512; e += 256) {
            int r = e >> 6, j = e & 63;
            float s = Acc[r * P + j];
            #pragma unroll 8
            for (int d = 0; d < 64; ++d) s += Acc[(16 + r) * P + d] * Wst[d * 64 + j];
            Acc[r * P + j] = s;
        }
        __syncthreads();
    }

    if (tx < 24) {
        int r = tx / 3, k = tx % 3;
        float s = __ldg(p.bc + k);
        #pragma unroll 8
        for (int d = 0; d < 64; ++d)
            s += fmaxf(Acc[r * P + d], 0.f) * __ldg(p.Wc + d * 3 + k);
        out[COLOR_OFF + (size_t)(rb * 8 + r) * 3 + k] = s;
    }
}

extern "C" void kernel_launch(void* const* d_in, const int* in_sizes, int n_in,
                              void* d_out, int out_size) {
    (void)in_sizes; (void)n_in; (void)out_size;
    Params prm;
    prm.query  = (const float*)d_in[0];
    prm.latent = (const float*)d_in[1];
    prm.W1     = (const float*)d_in[2];
    prm.b1     = (const float*)d_in[3];
    prm.Wq     = (const float*)d_in[4];
    prm.bq     = (const float*)d_in[5];
    prm.Wk     = (const float*)d_in[6];
    prm.bk     = (const float*)d_in[7];
    prm.Wv     = (const float*)d_in[8];
    prm.bv     = (const float*)d_in[9];
    prm.Wo     = (const float*)d_in[10];
    prm.bo     = (const float*)d_in[11];
    prm.fW1    = (const float*)d_in[12];
    prm.fb1    = (const float*)d_in[13];
    prm.fW2    = (const float*)d_in[14];
    prm.fb2    = (const float*)d_in[15];
    prm.g1     = (const float*)d_in[16];
    prm.be1    = (const float*)d_in[17];
    prm.g2     = (const float*)d_in[18];
    prm.be2    = (const float*)d_in[19];
    prm.cWq    = (const float*)d_in[20];
    prm.cbq    = (const float*)d_in[21];
    prm.cWk    = (const float*)d_in[22];
    prm.cbk    = (const float*)d_in[23];
    prm.cWv    = (const float*)d_in[24];
    prm.cbv    = (const float*)d_in[25];
    prm.cWo    = (const float*)d_in[26];
    prm.cbo    = (const float*)d_in[27];
    prm.Wc     = (const float*)d_in[28];
    prm.bc     = (const float*)d_in[29];
    prm.Wsig   = (const float*)d_in[30];
    prm.bs     = (const float*)d_in[31];

    cudaFuncSetAttribute(radiance_fused_kernel,
                         cudaFuncAttributeMaxDynamicSharedMemorySize, SMEM_BYTES);
    radiance_fused_kernel<<<B_RAYS / RAYS_CTA, 256, SMEM_BYTES>>>(prm, (float*)d_out);
}

// round 16
// speedup vs baseline: 2.9508x; 2.9508x over previous
#include <cuda_runtime.h>

// ---------------------------------------------------------------------------
// RadianceTransformer2 fully-fused fp32 kernel, v2.
// 1 CTA (512 threads) owns 16 rays = 128 tokens; all activations in smem.
// GEMM: thread = 2 tokens x 8 cols (conflict-free W reads, vectorized A).
// ---------------------------------------------------------------------------

#define B_RAYS   32768
#define RAYS_CTA 16
#define TOK      128
#define NTHREADS 512
#define P        68            // smem row pitch (floats)

// d_out layout: color (B*3), sigma (B), out (B*512), attn (B*1024)
#define COLOR_OFF 0
#define SIG_OFF   ((size_t)B_RAYS * 3)
#define OUT_OFF   ((size_t)B_RAYS * 4)
#define ATTN_OFF  ((size_t)B_RAYS * 516)

// smem float offsets
#define XS_O   0
#define ACC_O  8704
#define QB_O   17408
#define KB_O   26112
#define VB_O   34816
#define WST_O  43520          // 64x64
#define PB_O   47616          // 128 x 9
#define QS_O   48768          // 16 x 68
#define SMEM_FLOATS 49856
#define SMEM_BYTES  (SMEM_FLOATS * 4)   // 199,424 B

typedef unsigned long long u64;

__device__ __forceinline__ u64 pk2(float x, float y) {
    u64 r; asm("mov.b64 %0, {%1,%2};" : "=l"(r) : "f"(x), "f"(y)); return r;
}
__device__ __forceinline__ void up2(u64 v, float& x, float& y) {
    asm("mov.b64 {%0,%1}, %2;" : "=f"(x), "=f"(y) : "l"(v));
}
__device__ __forceinline__ void fma2(u64& a, u64 b, u64 c) {
    asm("fma.rn.f32x2 %0, %1, %2, %0;" : "+l"(a) : "l"(b), "l"(c));
}

struct Params {
    const float *query, *latent, *W1, *b1;
    const float *Wq, *bq, *Wk, *bk, *Wv, *bv, *Wo, *bo;
    const float *fW1, *fb1, *fW2, *fb2;
    const float *g1, *be1, *g2, *be2;
    const float *cWq, *cbq, *cWk, *cbk, *cWv, *cbv, *cWo, *cbo;
    const float *Wc, *bc, *Wsig, *bs;
};

// Stage a 64x64 weight tile (row stride `stride` floats) into Wst[64][64]
__device__ __forceinline__ void stagew(float* Wst, const float* __restrict__ src, int stride) {
    int tx = threadIdx.x;
    #pragma unroll
    for (int rep = 0; rep < 2; ++rep) {
        int i = rep * NTHREADS + tx;
        int d = i >> 4, cv = (i & 15) << 2;
        *(float4*)(Wst + d * 64 + cv) = __ldg((const float4*)(src + (size_t)d * stride + cv));
    }
}

// C[128x64(pitch P)] = (ACC ? C : bias) + A[128x64(pitch P)] @ Wst[64x64]
// thread = 2 tokens x 8 cols (cols g*4..g*4+3 and 32+g*4..32+g*4+3)
template <bool ACC, bool RELU>
__device__ __forceinline__ void gemm128(const float* __restrict__ A,
                                        const float* __restrict__ Wst,
                                        const float* __restrict__ biasg,
                                        float* __restrict__ C) {
    const int tx = threadIdx.x;
    const int tp = tx >> 3;        // token pair 0..63
    const int g  = tx & 7;         // col group 0..7
    const int t0 = tp * 2;
    const int c0 = g * 4;
    const int c1 = 32 + g * 4;
    u64 acc[8];   // [0..1]=t0/c0, [2..3]=t0/c1, [4..5]=t1/c0, [6..7]=t1/c1
    if (ACC) {
        ulonglong2 v;
        v = *(const ulonglong2*)(C + t0 * P + c0);       acc[0] = v.x; acc[1] = v.y;
        v = *(const ulonglong2*)(C + t0 * P + c1);       acc[2] = v.x; acc[3] = v.y;
        v = *(const ulonglong2*)(C + (t0 + 1) * P + c0); acc[4] = v.x; acc[5] = v.y;
        v = *(const ulonglong2*)(C + (t0 + 1) * P + c1); acc[6] = v.x; acc[7] = v.y;
    } else {
        float2 b0 = __ldg((const float2*)(biasg + c0));
        float2 b1 = __ldg((const float2*)(biasg + c0 + 2));
        float2 b2 = __ldg((const float2*)(biasg + c1));
        float2 b3 = __ldg((const float2*)(biasg + c1 + 2));
        acc[0] = pk2(b0.x, b0.y); acc[1] = pk2(b1.x, b1.y);
        acc[2] = pk2(b2.x, b2.y); acc[3] = pk2(b3.x, b3.y);
        acc[4] = acc[0]; acc[5] = acc[1]; acc[6] = acc[2]; acc[7] = acc[3];
    }
    const float* a0 = A + t0 * P;
    const float* a1 = a0 + P;
    #pragma unroll 4
    for (int d4 = 0; d4 < 16; ++d4) {
        float4 x0 = *(const float4*)(a0 + d4 * 4);
        float4 x1 = *(const float4*)(a1 + d4 * 4);
        #pragma unroll
        for (int dd = 0; dd < 4; ++dd) {
            int d = d4 * 4 + dd;
            ulonglong2 wA = *(const ulonglong2*)(Wst + d * 64 + c0);
            ulonglong2 wB = *(const ulonglong2*)(Wst + d * 64 + c1);
            float e0 = (&x0.x)[dd];
            float e1 = (&x1.x)[dd];
            u64 p0 = pk2(e0, e0);
            u64 p1 = pk2(e1, e1);
            fma2(acc[0], p0, wA.x); fma2(acc[1], p0, wA.y);
            fma2(acc[2], p0, wB.x); fma2(acc[3], p0, wB.y);
            fma2(acc[4], p1, wA.x); fma2(acc[5], p1, wA.y);
            fma2(acc[6], p1, wB.x); fma2(acc[7], p1, wB.y);
        }
    }
    if (RELU) {
        #pragma unroll
        for (int k = 0; k < 8; ++k) {
            float x, y; up2(acc[k], x, y);
            acc[k] = pk2(fmaxf(x, 0.f), fmaxf(y, 0.f));
        }
    }
    *(ulonglong2*)(C + t0 * P + c0)       = make_ulonglong2(acc[0], acc[1]);
    *(ulonglong2*)(C + t0 * P + c1)       = make_ulonglong2(acc[2], acc[3]);
    *(ulonglong2*)(C + (t0 + 1) * P + c0) = make_ulonglong2(acc[4], acc[5]);
    *(ulonglong2*)(C + (t0 + 1) * P + c1) = make_ulonglong2(acc[6], acc[7]);
}

// Qb[128x64] = P[128x8] @ Vb (per-ray 8x8 attention applied to V)
__device__ __forceinline__ void pv128(const float* __restrict__ Pb,
                                      const float* __restrict__ Vb,
                                      float* __restrict__ Qb) {
    const int tx = threadIdx.x;
    const int tp = tx >> 3;
    const int g  = tx & 7;
    const int t0 = tp * 2;
    const int c0 = g * 4;
    const int c1 = 32 + g * 4;
    const int rbase = t0 & ~7;     // ray base row (both tokens in same ray)
    u64 acc[8];
    #pragma unroll
    for (int k = 0; k < 8; ++k) acc[k] = 0ull;
    #pragma unroll
    for (int j = 0; j < 8; ++j) {
        float q0 = Pb[t0 * 9 + j];
        float q1 = Pb[(t0 + 1) * 9 + j];
        u64 p0 = pk2(q0, q0);
        u64 p1 = pk2(q1, q1);
        ulonglong2 vA = *(const ulonglong2*)(Vb + (rbase + j) * P + c0);
        ulonglong2 vB = *(const ulonglong2*)(Vb + (rbase + j) * P + c1);
        fma2(acc[0], p0, vA.x); fma2(acc[1], p0, vA.y);
        fma2(acc[2], p0, vB.x); fma2(acc[3], p0, vB.y);
        fma2(acc[4], p1, vA.x); fma2(acc[5], p1, vA.y);
        fma2(acc[6], p1, vB.x); fma2(acc[7], p1, vB.y);
    }
    *(ulonglong2*)(Qb + t0 * P + c0)       = make_ulonglong2(acc[0], acc[1]);
    *(ulonglong2*)(Qb + t0 * P + c1)       = make_ulonglong2(acc[2], acc[3]);
    *(ulonglong2*)(Qb + (t0 + 1) * P + c0) = make_ulonglong2(acc[4], acc[5]);
    *(ulonglong2*)(Qb + (t0 + 1) * P + c1) = make_ulonglong2(acc[6], acc[7]);
}

// Xs = LayerNorm(Acc + Xs) * g + b  (one thread per 64-wide token row)
__device__ __forceinline__ void ln_res(float* __restrict__ Xs, const float* __restrict__ Acc,
                                       const float* __restrict__ gg, const float* __restrict__ bb) {
    int tx = threadIdx.x;
    if (tx < TOK) {
        const float4* x4 = (const float4*)(Xs + tx * P);
        const float4* a4 = (const float4*)(Acc + tx * P);
        float s = 0.f, s2 = 0.f;
        #pragma unroll
        for (int q = 0; q < 16; ++q) {
            float4 x = x4[q], a = a4[q];
            float v0 = x.x + a.x, v1 = x.y + a.y, v2 = x.z + a.z, v3 = x.w + a.w;
            s  += (v0 + v1) + (v2 + v3);
            s2 += v0 * v0 + v1 * v1 + v2 * v2 + v3 * v3;
        }
        float mean = s * 0.015625f;
        float var  = s2 * 0.015625f - mean * mean;
        float w = rsqrtf(var + 1e-5f);
        float4* xo = (float4*)(Xs + tx * P);
        const float4* g4 = (const float4*)gg;
        const float4* b4 = (const float4*)bb;
        #pragma unroll
        for (int q = 0; q < 16; ++q) {
            float4 x = x4[q], a = a4[q];
            float4 g = __ldg(g4 + q), b = __ldg(b4 + q);
            float4 o;
            o.x = (x.x + a.x - mean) * w * g.x + b.x;
            o.y = (x.y + a.y - mean) * w * g.y + b.y;
            o.z = (x.z + a.z - mean) * w * g.z + b.z;
            o.w = (x.w + a.w - mean) * w * g.w + b.w;
            xo[q] = o;
        }
    }
}

__global__ void __launch_bounds__(NTHREADS, 1)
radiance_fused_kernel(Params p, float* __restrict__ out) {
    extern __shared__ float sm[];
    float* Xs  = sm + XS_O;
    float* Acc = sm + ACC_O;
    float* Qb  = sm + QB_O;
    float* Kb  = sm + KB_O;
    float* Vb  = sm + VB_O;
    float* Wst = sm + WST_O;
    float* Pb  = sm + PB_O;
    float* qs  = sm + QS_O;

    const int rb = blockIdx.x;          // ray-block: rays rb*16 .. rb*16+15
    const int tx = threadIdx.x;

    // ---------------- layer 0: Xs = relu(latent @ W1 + b1) ----------------
    for (int i = tx; i < TOK * 64; i += NTHREADS)
        Acc[(i >> 6) * P + (i & 63)] = __ldg(p.b1 + (i & 63));
    for (int c = 0; c < 8; ++c) {
        __syncthreads();
        stagew(Wst, p.W1 + c * 64 * 64, 64);
        #pragma unroll
        for (int rep = 0; rep < 4; ++rep) {
            int i = rep * NTHREADS + tx;
            int row = i >> 4, cv = (i & 15) << 2;
            *(float4*)(Xs + row * P + cv) =
                __ldg((const float4*)(p.latent + ((size_t)(rb * TOK + row)) * 512 + c * 64 + cv));
        }
        __syncthreads();
        gemm128<true, false>(Xs, Wst, nullptr, Acc);
    }
    __syncthreads();
    for (int i = tx; i < TOK * 64; i += NTHREADS) {
        int t = i >> 6, j = i & 63;
        Xs[t * P + j] = fmaxf(Acc[t * P + j], 0.f);
    }
    __syncthreads();

    // ---------------- 4 transformer layers ----------------
    for (int l = 0; l < 4; ++l) {
        for (int i = tx; i < TOK * 64; i += NTHREADS)
            Acc[(i >> 6) * P + (i & 63)] = __ldg(p.bo + l * 64 + (i & 63));
        __syncthreads();

        for (int h = 0; h < 4; ++h) {
            stagew(Wst, p.Wq + (size_t)l * 64 * 256 + h * 64, 256); __syncthreads();
            gemm128<false, false>(Xs, Wst, p.bq + l * 256 + h * 64, Qb); __syncthreads();
            stagew(Wst, p.Wk + (size_t)l * 64 * 256 + h * 64, 256); __syncthreads();
            gemm128<false, false>(Xs, Wst, p.bk + l * 256 + h * 64, Kb); __syncthreads();
            stagew(Wst, p.Wv + (size_t)l * 64 * 256 + h * 64, 256); __syncthreads();
            gemm128<false, false>(Xs, Wst, p.bv + l * 256 + h * 64, Vb); __syncthreads();

            // scores: 16 rays x 8 x 8
            for (int e = tx; e < 1024; e += NTHREADS) {
                int r = e >> 6, qi = (e >> 3) & 7, kj = e & 7;
                const float4* q4 = (const float4*)(Qb + (r * 8 + qi) * P);
                const float4* k4 = (const float4*)(Kb + (r * 8 + kj) * P);
                float s = 0.f;
                #pragma unroll
                for (int d = 0; d < 16; ++d) {
                    float4 a = q4[d], b = k4[d];
                    s += a.x * b.x + a.y * b.y + a.z * b.z + a.w * b.w;
                }
                Pb[(r * 8 + qi) * 9 + kj] = s * 0.125f;
            }
            __syncthreads();

            // softmax + write attn probs (one thread per (ray, qi) row)
            if (tx < TOK) {
                float* pr = Pb + tx * 9;
                float m = pr[0];
                #pragma unroll
                for (int j = 1; j < 8; ++j) m = fmaxf(m, pr[j]);
                float ex[8]; float ssum = 0.f;
                #pragma unroll
                for (int j = 0; j < 8; ++j) { float e = expf(pr[j] - m); ex[j] = e; ssum += e; }
                float inv = 1.f / ssum;
                int rayg = rb * RAYS_CTA + (tx >> 3);
                int qi = tx & 7;
                size_t base = ATTN_OFF + (size_t)rayg * 1024 + (size_t)l * 256 + h * 64 + qi * 8;
                #pragma unroll
                for (int j = 0; j < 8; ++j) { float v = ex[j] * inv; pr[j] = v; out[base + j] = v; }
            }
            __syncthreads();

            pv128(Pb, Vb, Qb);                // Qb := per-head attention output
            __syncthreads();
            stagew(Wst, p.Wo + (size_t)l * 256 * 64 + h * 64 * 64, 64); __syncthreads();
            gemm128<true, false>(Qb, Wst, nullptr, Acc);    // Acc += head @ Wo_h
            __syncthreads();
        }

        ln_res(Xs, Acc, p.g1 + l * 64, p.be1 + l * 64); __syncthreads();

        stagew(Wst, p.fW1 + (size_t)l * 64 * 64, 64); __syncthreads();
        gemm128<false, true>(Xs, Wst, p.fb1 + l * 64, Qb); __syncthreads();
        stagew(Wst, p.fW2 + (size_t)l * 64 * 64, 64); __syncthreads();
        gemm128<false, false>(Qb, Wst, p.fb2 + l * 64, Acc); __syncthreads();

        ln_res(Xs, Acc, p.g2 + l * 64, p.be2 + l * 64); __syncthreads();
    }

    // ---------------- out copy ----------------
    #pragma unroll
    for (int rep = 0; rep < 4; ++rep) {
        int i = rep * NTHREADS + tx;
        int row = i >> 4, cv = (i & 15) << 2;
        *(float4*)(out + OUT_OFF + (size_t)(rb * TOK + row) * 64 + cv) =
            *(const float4*)(Xs + row * P + cv);
    }

    // ---------------- sigma = max_t(out) @ Wsig + bs ----------------
    if (tx < TOK) {                          // 16 rays x 8 col-groups
        int r = tx >> 3, jg = tx & 7;
        float s = 0.f;
        #pragma unroll
        for (int jj = 0; jj < 8; ++jj) {
            int j = jg * 8 + jj;
            float m = Xs[(r * 8) * P + j];
            #pragma unroll
            for (int t = 1; t < 8; ++t) m = fmaxf(m, Xs[(r * 8 + t) * P + j]);
            s += m * __ldg(p.Wsig + j);
        }
        Pb[r * 9 + jg] = s;
    }
    __syncthreads();
    if (tx < RAYS_CTA) {
        float s = __ldg(p.bs);
        #pragma unroll
        for (int jg = 0; jg < 8; ++jg) s += Pb[tx * 9 + jg];
        out[SIG_OFF + (size_t)rb * RAYS_CTA + tx] = s;
    }

    // ---------------- cross attention + color ----------------
    if (tx < RAYS_CTA * 16) {                // 16 rays x 64 floats
        int r = tx >> 4, cv = (tx & 15) << 2;
        *(float4*)(qs + r * P + cv) =
            __ldg((const float4*)(p.query + (size_t)(rb * RAYS_CTA + r) * 64 + cv));
    }
    for (int e = tx; e < RAYS_CTA * 64; e += NTHREADS)
        Acc[(e >> 6) * P + (e & 63)] = __ldg(p.cbo + (e & 63));   // cAcc rows 0..15
    __syncthreads();

    for (int h = 0; h < 4; ++h) {
        // Qc (rows 16..31 of Acc)
        stagew(Wst, p.cWq + h * 64, 256); __syncthreads();
        for (int e = tx; e < RAYS_CTA * 64; e += NTHREADS) {
            int r = e >> 6, j = e & 63;
            float s = __ldg(p.cbq + h * 64 + j);
            #pragma unroll 8
            for (int d = 0; d < 64; ++d) s += qs[r * P + d] * Wst[d * 64 + j];
            Acc[(16 + r) * P + j] = s;
        }
        __syncthreads();
        stagew(Wst, p.cWk + h * 64, 256); __syncthreads();
        gemm128<false, false>(Xs, Wst, p.cbk + h * 64, Kb); __syncthreads();
        stagew(Wst, p.cWv + h * 64, 256); __syncthreads();
        gemm128<false, false>(Xs, Wst, p.cbv + h * 64, Vb); __syncthreads();

        if (tx < TOK) {                      // 16 rays x 8 keys
            int r = tx >> 3, j = tx & 7;
            const float4* q4 = (const float4*)(Acc + (16 + r) * P);
            const float4* k4 = (const float4*)(Kb + (r * 8 + j) * P);
            float s = 0.f;
            #pragma unroll
            for (int d = 0; d < 16; ++d) {
                float4 a = q4[d], b = k4[d];
                s += a.x * b.x + a.y * b.y + a.z * b.z + a.w * b.w;
            }
            Pb[r * 9 + j] = s * 0.125f;
        }
        __syncthreads();
        if (tx < RAYS_CTA) {
            float* pr = Pb + tx * 9;
            float m = pr[0];
            #pragma unroll
            for (int j = 1; j < 8; ++j) m = fmaxf(m, pr[j]);
            float ssum = 0.f;
            #pragma unroll
            for (int j = 0; j < 8; ++j) { float e = expf(pr[j] - m); pr[j] = e; ssum += e; }
            float inv = 1.f / ssum;
            #pragma unroll
            for (int j = 0; j < 8; ++j) pr[j] *= inv;
        }
        __syncthreads();
        // outh (rows 32..47 of Acc)
        for (int e = tx; e < RAYS_CTA * 64; e += NTHREADS) {
            int r = e >> 6, jc = e & 63;
            float s = 0.f;
            #pragma unroll
            for (int j = 0; j < 8; ++j) s += Pb[r * 9 + j] * Vb[(r * 8 + j) * P + jc];
            Acc[(32 + r) * P + jc] = s;
        }
        __syncthreads();
        stagew(Wst, p.cWo + h * 64 * 64, 64); __syncthreads();
        for (int e = tx; e < RAYS_CTA * 64; e += NTHREADS) {
            int r = e >> 6, j = e & 63;
            float s = Acc[r * P + j];
            #pragma unroll 8
            for (int d = 0; d < 64; ++d) s += Acc[(32 + r) * P + d] * Wst[d * 64 + j];
            Acc[r * P + j] = s;
        }
        __syncthreads();
    }

    if (tx < RAYS_CTA * 3) {
        int r = tx / 3, k = tx % 3;
        float s = __ldg(p.bc + k);
        #pragma unroll 8
        for (int d = 0; d < 64; ++d)
            s += fmaxf(Acc[r * P + d], 0.f) * __ldg(p.Wc + d * 3 + k);
        out[COLOR_OFF + (size_t)(rb * RAYS_CTA + r) * 3 + k] = s;
    }
}

extern "C" void kernel_launch(void* const* d_in, const int* in_sizes, int n_in,
                              void* d_out, int out_size) {
    (void)in_sizes; (void)n_in; (void)out_size;
    Params prm;
    prm.query  = (const float*)d_in[0];
    prm.latent = (const float*)d_in[1];
    prm.W1     = (const float*)d_in[2];
    prm.b1     = (const float*)d_in[3];
    prm.Wq     = (const float*)d_in[4];
    prm.bq     = (const float*)d_in[5];
    prm.Wk     = (const float*)d_in[6];
    prm.bk     = (const float*)d_in[7];
    prm.Wv     = (const float*)d_in[8];
    prm.bv     = (const float*)d_in[9];
    prm.Wo     = (const float*)d_in[10];
    prm.bo     = (const float*)d_in[11];
    prm.fW1    = (const float*)d_in[12];
    prm.fb1    = (const float*)d_in[13];
    prm.fW2    = (const float*)d_in[14];
    prm.fb2    = (const float*)d_in[15];
    prm.g1     = (const float*)d_in[16];
    prm.be1    = (const float*)d_in[17];
    prm.g2     = (const float*)d_in[18];
    prm.be2    = (const float*)d_in[19];
    prm.cWq    = (const float*)d_in[20];
    prm.cbq    = (const float*)d_in[21];
    prm.cWk    = (const float*)d_in[22];
    prm.cbk    = (const float*)d_in[23];
    prm.cWv    = (const float*)d_in[24];
    prm.cbv    = (const float*)d_in[25];
    prm.cWo    = (const float*)d_in[26];
    prm.cbo    = (const float*)d_in[27];
    prm.Wc     = (const float*)d_in[28];
    prm.bc     = (const float*)d_in[29];
    prm.Wsig   = (const float*)d_in[30];
    prm.bs     = (const float*)d_in[31];

    cudaFuncSetAttribute(radiance_fused_kernel,
                         cudaFuncAttributeMaxDynamicSharedMemorySize, SMEM_BYTES);
    radiance_fused_kernel<<<B_RAYS / RAYS_CTA, NTHREADS, SMEM_BYTES>>>(prm, (float*)d_out);
}